// round 8
// baseline (speedup 1.0000x reference)
#include <cuda_runtime.h>
#include <cstdint>
#include <cstddef>

// Problem dims
#define T_DIM 1024
#define H_DIM 512
#define B_DIM 64
#define NBLK  144
#define THR   256
#define DYN_SMEM (68 * 1024)

// ---------------------------------------------------------------------------
// Device-global scratch (~3.6MB)
// ---------------------------------------------------------------------------
__device__ float g_z[18 * B_DIM * H_DIM];       // z[m][b][h] pre-activations
__device__ float g_l[B_DIM * 8 * H_DIM];        // l[b][k][h]
__device__ float g_hT[H_DIM * B_DIM];           // h transposed: hT[h][b]
__device__ unsigned g_flags[NBLK];
__device__ unsigned g_epoch;

// ---------------------------------------------------------------------------
// f32x2 helpers
// ---------------------------------------------------------------------------
__device__ __forceinline__ unsigned long long pack2(float v) {
    unsigned long long r;
    asm("mov.b64 %0, {%1, %1};" : "=l"(r) : "f"(v));
    return r;
}
__device__ __forceinline__ unsigned long long fma2(unsigned long long a,
                                                   unsigned long long b,
                                                   unsigned long long c) {
    unsigned long long d;
    asm("fma.rn.f32x2 %0, %1, %2, %3;" : "=l"(d) : "l"(a), "l"(b), "l"(c));
    return d;
}
__device__ __forceinline__ float2 unpack2(unsigned long long v) {
    float2 f;
    asm("mov.b64 {%0, %1}, %2;" : "=f"(f.x), "=f"(f.y) : "l"(v));
    return f;
}

__device__ __forceinline__ float fsig(float x) {
    x = fminf(fmaxf(x, -30.f), 30.f);
    return 1.f / (1.f + __expf(-x));
}
__device__ __forceinline__ float ftanh(float x) {
    x = fminf(fmaxf(x, -15.f), 15.f);
    float e = __expf(2.f * x);
    return (e - 1.f) / (e + 1.f);
}

struct Ptrs { const float* p[28]; };

// Input-projection metadata for matrix m.
__device__ __forceinline__ void matInfo(const Ptrs& P, int m,
                                        const float*& W, const float*& bias,
                                        const float*& X, int& C) {
    if (m < 4) {
        C = 8; X = P.p[0];
        W = P.p[8 + 3 * m]; bias = P.p[10 + 3 * m];
    } else if (m < 11) {
        int k = m - 4; C = 3;
        X = P.p[(k == 0) ? 1 : 2];                 // aux input gates: x1 then x2 (faithful quirk)
        W = P.p[20] + (size_t)k * 3 * H_DIM; bias = P.p[22] + (size_t)k * H_DIM;
    } else {
        int k = m - 11; C = 3;
        X = P.p[1 + k];                            // aux candidates: x1..x7
        W = P.p[23] + (size_t)k * 3 * H_DIM; bias = P.p[25] + (size_t)k * H_DIM;
    }
}
// Recurrent matrix U_m base pointer (ORIGINAL [h][j] layout).
__device__ __forceinline__ const float* Uptr(const Ptrs& P, int m) {
    if (m < 4)  return P.p[9 + 3 * m];
    if (m < 11) return P.p[21] + (size_t)(m - 4)  * H_DIM * H_DIM;
    return             P.p[24] + (size_t)(m - 11) * H_DIM * H_DIM;
}

// ---------------------------------------------------------------------------
__global__ void reset_kernel() {
    int i = blockIdx.x * blockDim.x + threadIdx.x;
    int n = gridDim.x * blockDim.x;
    if (i == 0) g_epoch = 0u;
    if (i < NBLK) g_flags[i] = 0u;
    for (int k = i; k < H_DIM * B_DIM; k += n) g_hT[k] = 0.f;
}

// ---------------------------------------------------------------------------
// Flag-array epoch grid barrier.
// ---------------------------------------------------------------------------
__device__ __forceinline__ void grid_barrier(unsigned target) {
    __syncthreads();
    if (threadIdx.x == 0) {
        __threadfence();
        *(volatile unsigned*)&g_flags[blockIdx.x] = target;
    }
    if (blockIdx.x == 0) {
        if (threadIdx.x < NBLK) {
            while (*(volatile unsigned*)&g_flags[threadIdx.x] < target) __nanosleep(64);
        }
        __syncthreads();
        if (threadIdx.x == 0) {
            __threadfence();
            *(volatile unsigned*)&g_epoch = target;
        }
    }
    if (threadIdx.x == 0) {
        while (*(volatile unsigned*)&g_epoch < target) __nanosleep(64);
        __threadfence();
    }
    __syncthreads();
}

// ---------------------------------------------------------------------------
// Persistent recurrent kernel, 144 CTAs x 256 threads, 68KB dynamic smem.
//
// Phase A: cta = m*8 + jb (18 mats x 8 j-tiles). Thread = bq(8) x jl(32):
//   2 j (jl, jl+32) x 8 batches. K-chunked 8 x 64h, double-buffered.
//   Writes raw z[m][b][j] (incl. input projection + bias).
// Mid:     all threads materialize l[b][k][h] = sig(z_i)*tanh(z_c).
// Phase B (cta<128): cta = bt(8) x gt(16); thread = bloc(8) x gloc(32);
//   owns one (b,g), all 8 gates; c kept in register. f/o applied from z.
// ---------------------------------------------------------------------------
__global__ void __launch_bounds__(THR, 1)
main_kernel(Ptrs P, float* __restrict__ out) {
    extern __shared__ __align__(16) char dyn[];
    // phase A layout
    float*  sU = (float*)dyn;                     // [2][64*64]   32KB
    float*  sH = (float*)(dyn + 32768);           // [2][64*64]   32KB
    float*  sX = (float*)(dyn + 65536);           // [64*8]        2KB
    // phase B overlay
    float2* sL = (float2*)dyn;                    // [2][2048]    32KB
    float*  sW = (float*)(dyn + 32768);           // [2][2048]    16KB

    const int cta = blockIdx.x, tid = threadIdx.x;

    // --- phase A ids ---
    const int m   = cta >> 3;                 // 0..17
    const int jb  = cta & 7;                  // 0..7
    const int jl  = tid & 31;
    const int bq  = tid >> 5;                 // 0..7 (8 batches each)
    const int j0  = jb * 64 + jl;
    const int j1  = j0 + 32;

    const float *Wp, *bp, *Xp;
    int C;
    matInfo(P, m, Wp, bp, Xp, C);
    float w0[8], w1[8];
    #pragma unroll
    for (int c = 0; c < 8; c++) { w0[c] = 0.f; w1[c] = 0.f; }
    for (int c = 0; c < C; c++) {
        w0[c] = Wp[(size_t)c * H_DIM + j0];
        w1[c] = Wp[(size_t)c * H_DIM + j1];
    }
    const float bias0 = bp[j0], bias1 = bp[j1];
    const float* Ub = Uptr(P, m) + jb * 64;    // row h: 64 consecutive j

    // --- phase B ids ---
    const int btB   = cta >> 4;                // 0..7 (cta<128)
    const int gtB   = cta & 15;
    const int blocB = tid >> 5;                // 0..7
    const int glocB = tid & 31;
    const int bB_   = btB * 8 + blocB;
    const int gB    = gtB * 32 + glocB;
    const float* W_a = P.p[26] + gtB * 32;
    const float  baB = P.p[27][gB & (H_DIM - 1)];
    float c_reg = 0.f;

    float4 uR[4], hR[4];
    float2 lR[8]; float4 wR[2];

#define LD_A(ck) do { \
    _Pragma("unroll") \
    for (int r = 0; r < 4; r++) { int i = tid + r * THR; \
        int hh = i >> 4, f4 = i & 15; \
        uR[r] = __ldg((const float4*)(Ub + (size_t)((ck) * 64 + hh) * H_DIM) + f4); \
        hR[r] = __ldcg((const float4*)(g_hT + ((ck) * 64 + hh) * B_DIM) + f4); } \
} while (0)
#define ST_A(buf) do { \
    _Pragma("unroll") \
    for (int r = 0; r < 4; r++) { int i = tid + r * THR; \
        ((float4*)(sU + (buf) * 4096))[i] = uR[r]; \
        ((float4*)(sH + (buf) * 4096))[i] = hR[r]; } \
} while (0)
#define LD_B(ck) do { \
    _Pragma("unroll") \
    for (int r = 0; r < 8; r++) { int i = tid + r * THR; \
        int hh = i & 63, rr = i >> 6, k2 = rr & 3, bl = rr >> 2; \
        const float* src = &g_l[(((btB * 8 + bl) * 8 + 2 * k2) << 9) + (ck) * 64 + hh]; \
        lR[r] = make_float2(__ldcg(src), __ldcg(src + H_DIM)); } \
    _Pragma("unroll") \
    for (int r = 0; r < 2; r++) { int i = tid + r * THR; \
        int hh = i >> 3, f4 = i & 7; \
        wR[r] = __ldg((const float4*)(W_a + (size_t)((ck) * 64 + hh) * H_DIM) + f4); } \
} while (0)
#define ST_B(buf) do { \
    _Pragma("unroll") \
    for (int r = 0; r < 8; r++) { int i = tid + r * THR; \
        int hh = i & 63, rr = i >> 6, k2 = rr & 3, bl = rr >> 2; \
        (sL + (buf) * 2048)[(bl * 64 + hh) * 4 + k2] = lR[r]; } \
    _Pragma("unroll") \
    for (int r = 0; r < 2; r++) { int i = tid + r * THR; \
        ((float4*)(sW + (buf) * 2048))[i] = wR[r]; } \
} while (0)

    for (int t = 0; t < T_DIM; t++) {
        // =============== Phase A: z = x@W + b + h@U (one matrix) ==========
        unsigned long long accA[4], accB[4];
        #pragma unroll
        for (int i = 0; i < 4; i++) { accA[i] = 0ull; accB[i] = 0ull; }

        LD_A(0);
        for (int i = tid; i < 64 * C; i += THR) {
            int b = i / C, c = i - b * C;
            sX[b * 8 + c] = Xp[((size_t)b * C + c) * T_DIM + t];
        }
        ST_A(0);
        __syncthreads();

        #pragma unroll 1
        for (int ck = 0; ck < 8; ck++) {
            if (ck < 7) LD_A(ck + 1);
            const float* U0 = sU + (ck & 1) * 4096;
            const ulonglong2* Hv = (const ulonglong2*)(sH + (ck & 1) * 4096);
            #pragma unroll 8
            for (int hh = 0; hh < 64; hh++) {
                unsigned long long u0 = pack2(U0[hh * 64 + jl]);
                unsigned long long u1 = pack2(U0[hh * 64 + jl + 32]);
                ulonglong2 hv0 = Hv[hh * 16 + bq * 2 + 0];
                ulonglong2 hv1 = Hv[hh * 16 + bq * 2 + 1];
                accA[0] = fma2(hv0.x, u0, accA[0]);
                accA[1] = fma2(hv0.y, u0, accA[1]);
                accA[2] = fma2(hv1.x, u0, accA[2]);
                accA[3] = fma2(hv1.y, u0, accA[3]);
                accB[0] = fma2(hv0.x, u1, accB[0]);
                accB[1] = fma2(hv0.y, u1, accB[1]);
                accB[2] = fma2(hv1.x, u1, accB[2]);
                accB[3] = fma2(hv1.y, u1, accB[3]);
            }
            if (ck < 7) { __syncthreads(); ST_A((ck + 1) & 1); __syncthreads(); }
        }

        // epilogue: add input projection + bias, store raw z (8 batches x 2 j)
        #pragma unroll
        for (int q = 0; q < 4; q++) {
            int b0 = bq * 8 + 2 * q, b1 = b0 + 1;
            float p00 = bias0, p01 = bias0, p10 = bias1, p11 = bias1;
            for (int c = 0; c < C; c++) {
                float x0 = sX[b0 * 8 + c], x1 = sX[b1 * 8 + c];
                p00 = fmaf(x0, w0[c], p00);
                p01 = fmaf(x1, w0[c], p01);
                p10 = fmaf(x0, w1[c], p10);
                p11 = fmaf(x1, w1[c], p11);
            }
            float2 aa = unpack2(accA[q]);
            float2 bb = unpack2(accB[q]);
            float* z0 = &g_z[((size_t)m * B_DIM + b0) * H_DIM];
            float* z1 = &g_z[((size_t)m * B_DIM + b1) * H_DIM];
            z0[j0] = aa.x + p00;
            z1[j0] = aa.y + p01;
            z0[j1] = bb.x + p10;
            z1[j1] = bb.y + p11;
        }

        grid_barrier(3 * t + 1);

        // =============== Mid: materialize l[b][k][h] ======================
        {
            int gid = cta * THR + tid;
            const int NT = NBLK * THR;
            for (int idx = gid; idx < B_DIM * 8 * H_DIM; idx += NT) {
                int h = idx & (H_DIM - 1);
                int r = idx >> 9;
                int k = r & 7;
                int b = r >> 3;
                int mi = (k == 0) ? 0 : (3 + k);
                int mc = (k == 0) ? 2 : (10 + k);
                float zi = __ldcg(&g_z[((size_t)mi * B_DIM + b) * H_DIM + h]);
                float zc = __ldcg(&g_z[((size_t)mc * B_DIM + b) * H_DIM + h]);
                g_l[idx] = fsig(zi) * ftanh(zc);
            }
        }

        grid_barrier(3 * t + 2);

        // =============== Phase B: a = l @ W_a ; softmax combine ===========
        if (cta < 128) {
            unsigned long long acc[4] = {0ull, 0ull, 0ull, 0ull};
            float lg[8];

            LD_B(0); ST_B(0); __syncthreads();

            #pragma unroll 1
            for (int ck = 0; ck < 8; ck++) {
                if (ck < 7) LD_B(ck + 1);
                const float* W0 = sW + (ck & 1) * 2048;
                const ulonglong2* Lv = (const ulonglong2*)(sL + (ck & 1) * 2048);
                if ((gB >> 6) == ck) {
                    int hl = gB & 63;
                    ulonglong2 v0 = Lv[(blocB * 64 + hl) * 2 + 0];
                    ulonglong2 v1 = Lv[(blocB * 64 + hl) * 2 + 1];
                    float2 q2;
                    q2 = unpack2(v0.x); lg[0] = q2.x; lg[1] = q2.y;
                    q2 = unpack2(v0.y); lg[2] = q2.x; lg[3] = q2.y;
                    q2 = unpack2(v1.x); lg[4] = q2.x; lg[5] = q2.y;
                    q2 = unpack2(v1.y); lg[6] = q2.x; lg[7] = q2.y;
                }
                #pragma unroll 8
                for (int hh = 0; hh < 64; hh++) {
                    unsigned long long w2 = pack2(W0[hh * 32 + glocB]);
                    ulonglong2 v0 = Lv[(blocB * 64 + hh) * 2 + 0];
                    ulonglong2 v1 = Lv[(blocB * 64 + hh) * 2 + 1];
                    acc[0] = fma2(v0.x, w2, acc[0]);
                    acc[1] = fma2(v0.y, w2, acc[1]);
                    acc[2] = fma2(v1.x, w2, acc[2]);
                    acc[3] = fma2(v1.y, w2, acc[3]);
                }
                if (ck < 7) { __syncthreads(); ST_B((ck + 1) & 1); __syncthreads(); }
            }

            float a[8];
            { float2 q2;
              q2 = unpack2(acc[0]); a[0] = q2.x; a[1] = q2.y;
              q2 = unpack2(acc[1]); a[2] = q2.x; a[3] = q2.y;
              q2 = unpack2(acc[2]); a[4] = q2.x; a[5] = q2.y;
              q2 = unpack2(acc[3]); a[6] = q2.x; a[7] = q2.y; }

            float u[8], mx = -1e30f;
            #pragma unroll
            for (int k = 0; k < 8; k++) {
                u[k] = ftanh(fmaf(a[k], c_reg, baB));
                mx = fmaxf(mx, u[k]);
            }
            float es = 0.f, L = 0.f;
            #pragma unroll
            for (int k = 0; k < 8; k++) {
                float e = __expf(u[k] - mx);
                es += e;
                L  += e * lg[k];
            }
            L /= es;
            float fv = fsig(__ldcg(&g_z[((size_t)1 * B_DIM + bB_) * H_DIM + gB]));
            float ov = fsig(__ldcg(&g_z[((size_t)3 * B_DIM + bB_) * H_DIM + gB]));
            c_reg = fmaf(fv, c_reg, L);
            float hn = ov * ftanh(c_reg);
            g_hT[gB * B_DIM + bB_] = hn;
            out[(size_t)B_DIM * H_DIM + ((size_t)bB_ * T_DIM + t) * H_DIM + gB] = hn;
            if (t == T_DIM - 1) out[bB_ * H_DIM + gB] = hn;
        }

        grid_barrier(3 * t + 3);
    }
#undef LD_A
#undef ST_A
#undef LD_B
#undef ST_B
}

// ---------------------------------------------------------------------------
extern "C" void kernel_launch(void* const* d_in, const int* in_sizes, int n_in,
                              void* d_out, int out_size) {
    (void)in_sizes; (void)n_in; (void)out_size;
    Ptrs P;
    for (int i = 0; i < 28; i++) P.p[i] = (const float*)d_in[i];

    cudaFuncSetAttribute(main_kernel,
                         cudaFuncAttributeMaxDynamicSharedMemorySize, DYN_SMEM);

    reset_kernel<<<64, 256>>>();
    main_kernel<<<NBLK, THR, DYN_SMEM>>>(P, (float*)d_out);
}

// round 11
// speedup vs baseline: 1.1461x; 1.1461x over previous
#include <cuda_runtime.h>
#include <cstdint>
#include <cstddef>

#define T_DIM 1024
#define H_DIM 512
#define B_DIM 64
#define NBLK  144
#define THR   512
#define DYN_SMEM 135168

// ---------------------------------------------------------------------------
// Device-global scratch
// ---------------------------------------------------------------------------
__device__ float g_l[B_DIM * H_DIM * 8];        // l[b][h][k]  (k contiguous)
__device__ float g_f[B_DIM * H_DIM];            // f[b][h] (sigmoided)
__device__ float g_o[B_DIM * H_DIM];            // o[b][h] (sigmoided)
__device__ float g_hT[H_DIM * B_DIM];           // hT[h][b]
__device__ volatile unsigned g_flags[NBLK];
__device__ volatile unsigned g_epoch;

// ---------------------------------------------------------------------------
// f32x2 helpers
// ---------------------------------------------------------------------------
__device__ __forceinline__ unsigned long long pack2(float v) {
    unsigned long long r;
    asm("mov.b64 %0, {%1, %1};" : "=l"(r) : "f"(v));
    return r;
}
__device__ __forceinline__ unsigned long long fma2(unsigned long long a,
                                                   unsigned long long b,
                                                   unsigned long long c) {
    unsigned long long d;
    asm("fma.rn.f32x2 %0, %1, %2, %3;" : "=l"(d) : "l"(a), "l"(b), "l"(c));
    return d;
}
__device__ __forceinline__ float2 unpack2(unsigned long long v) {
    float2 f;
    asm("mov.b64 {%0, %1}, %2;" : "=f"(f.x), "=f"(f.y) : "l"(v));
    return f;
}

__device__ __forceinline__ float fsig(float x) {
    x = fminf(fmaxf(x, -30.f), 30.f);
    return 1.f / (1.f + __expf(-x));
}
__device__ __forceinline__ float ftanh(float x) {
    x = fminf(fmaxf(x, -15.f), 15.f);
    float e = __expf(2.f * x);
    return (e - 1.f) / (e + 1.f);
}

struct Ptrs { const float* p[28]; };

__device__ __forceinline__ void matInfo(const Ptrs& P, int m,
                                        const float*& W, const float*& bias,
                                        const float*& X, int& C) {
    if (m < 4) {
        C = 8; X = P.p[0];
        W = P.p[8 + 3 * m]; bias = P.p[10 + 3 * m];
    } else if (m < 11) {
        int k = m - 4; C = 3;
        X = P.p[(k == 0) ? 1 : 2];                 // aux input gates: x1 then x2 (faithful quirk)
        W = P.p[20] + (size_t)k * 3 * H_DIM; bias = P.p[22] + (size_t)k * H_DIM;
    } else {
        int k = m - 11; C = 3;
        X = P.p[1 + k];                            // aux candidates: x1..x7
        W = P.p[23] + (size_t)k * 3 * H_DIM; bias = P.p[25] + (size_t)k * H_DIM;
    }
}
__device__ __forceinline__ const float* Uptr(const Ptrs& P, int m) {
    if (m < 4)  return P.p[9 + 3 * m];
    if (m < 11) return P.p[21] + (size_t)(m - 4)  * H_DIM * H_DIM;
    return             P.p[24] + (size_t)(m - 11) * H_DIM * H_DIM;
}

// ---------------------------------------------------------------------------
__global__ void reset_kernel() {
    int i = blockIdx.x * blockDim.x + threadIdx.x;
    int n = gridDim.x * blockDim.x;
    if (i == 0) g_epoch = 0u;
    if (i < NBLK) g_flags[i] = 0u;
    for (int k = i; k < H_DIM * B_DIM; k += n) g_hT[k] = 0.f;
}

// ---------------------------------------------------------------------------
__device__ __forceinline__ void grid_barrier(unsigned target) {
    __syncthreads();
    if (threadIdx.x == 0) {
        __threadfence();
        g_flags[blockIdx.x] = target;
    }
    if (blockIdx.x == 0) {
        if (threadIdx.x < NBLK) {
            while (g_flags[threadIdx.x] < target) __nanosleep(64);
        }
        __syncthreads();
        if (threadIdx.x == 0) {
            __threadfence();
            g_epoch = target;
        }
    }
    if (threadIdx.x == 0) {
        while (g_epoch < target) __nanosleep(64);
        __threadfence();
    }
    __syncthreads();
}

// ---------------------------------------------------------------------------
// Persistent kernel: 144 CTAs x 512 threads, 132KB dynamic smem.
//
// Phase A: cta = p*16 + jt (9 gate pairs x 16 j-tiles of 32).
//   thread = kq(2: K half) x bq(8: 8 batches) x jl(32: 1 j), both mats.
//   4 staging iterations x (64h per K-half), double-buffered; split-K
//   reduced via smem exchange; epilogue computes l / f,o locally.
// Phase B (cta<128): cta = bt(8) x gt(16); thread = kq(2) x bloc(8) x gloc(32).
//   One (b,g), all 8 gates, half K; exchange-reduced; kq0 does softmax.
// ---------------------------------------------------------------------------
__global__ void __launch_bounds__(THR, 1)
main_kernel(Ptrs P, float* __restrict__ out) {
    extern __shared__ __align__(16) char dyn[];
    // phase A: sU [2buf][2kq][2mat][64hh][32j]  = 64KB @0
    //          sH [2buf][2kq][64hh][64b]        = 64KB @65536
    //          sX 2 x [64][8]                   =  4KB @131072
    // phase B: sL [2buf][2kq][8bl][64hh][8k]    = 64KB @0
    //          sW [2buf][2kq][64hh][32g]        = 32KB @65536
    // exchange (both phases): 16KB @0 (buf0 region; last compute uses buf1)
    float*  sU = (float*)dyn;
    float*  sH = (float*)(dyn + 65536);
    float*  sX = (float*)(dyn + 131072);
    float*  sL = (float*)dyn;
    float*  sW = (float*)(dyn + 65536);
    float4* sEx = (float4*)dyn;

    const int cta = blockIdx.x, tid = threadIdx.x;
    const int kq  = tid >> 8;                 // K half
    const int rec = tid & 255;

    // --- phase A ids ---
    const int p    = cta >> 4;
    const int jt   = cta & 15;
    const int jl   = tid & 31;
    const int bq   = (tid >> 5) & 7;
    const int j    = jt * 32 + jl;
    int ma, mb;
    if      (p == 0) { ma = 0; mb = 2; }
    else if (p == 1) { ma = 1; mb = 3; }
    else             { ma = 4 + (p - 2); mb = 11 + (p - 2); }

    const float *WA, *WB, *bAp, *bBp, *XA, *XB;
    int Ca, Cb;
    matInfo(P, ma, WA, bAp, XA, Ca);
    matInfo(P, mb, WB, bBp, XB, Cb);
    float wA[8], wB[8];
    #pragma unroll
    for (int c = 0; c < 8; c++) { wA[c] = 0.f; wB[c] = 0.f; }
    for (int c = 0; c < Ca; c++) wA[c] = WA[(size_t)c * H_DIM + j];
    for (int c = 0; c < Cb; c++) wB[c] = WB[(size_t)c * H_DIM + j];
    const float biasA = bAp[j], biasB = bBp[j];
    const float* Um[2] = { Uptr(P, ma) + jt * 32, Uptr(P, mb) + jt * 32 };

    // --- phase B ids ---
    const int bt    = cta >> 4;                // 0..7 (cta<128)
    const int gt    = cta & 15;
    const int bloc  = (tid >> 5) & 7;
    const int gloc  = tid & 31;
    const int bB_   = bt * 8 + bloc;
    const int gB    = gt * 32 + gloc;
    const int kq_own = gB >> 8;                // which K half holds l[..][gB]
    const int it_own = (gB >> 6) & 3;
    const float* W_a = P.p[26];
    const float  baB = P.p[27][gB & (H_DIM - 1)];
    float c_reg = 0.f;

    float4 uR[4], hR[4];
    float4 lR[4], wR2[2];

#define LD_A(it) do { \
    _Pragma("unroll") \
    for (int r = 0; r < 4; r++) { int i = tid + r * THR; \
        int kqs = i >> 10, mat = (i >> 9) & 1, hh = (i >> 3) & 63, f4 = i & 7; \
        uR[r] = __ldg((const float4*)(Um[mat] + (size_t)(kqs * 256 + (it) * 64 + hh) * H_DIM) + f4); } \
    _Pragma("unroll") \
    for (int r = 0; r < 4; r++) { int i = tid + r * THR; \
        int kqs = i >> 10, hh = (i >> 4) & 63, f4 = i & 15; \
        hR[r] = __ldcg((const float4*)(g_hT + (kqs * 256 + (it) * 64 + hh) * B_DIM) + f4); } \
} while (0)
#define ST_A(buf) do { \
    _Pragma("unroll") \
    for (int r = 0; r < 4; r++) { int i = tid + r * THR; \
        int kqs = i >> 10, mat = (i >> 9) & 1, hh = (i >> 3) & 63, f4 = i & 7; \
        ((float4*)sU)[(((buf) * 2 + kqs) * 2 + mat) * 512 + hh * 8 + f4] = uR[r]; } \
    _Pragma("unroll") \
    for (int r = 0; r < 4; r++) { int i = tid + r * THR; \
        int kqs = i >> 10, hh = (i >> 4) & 63, f4 = i & 15; \
        ((float4*)sH)[(((buf) * 2 + kqs) * 64 + hh) * 16 + f4] = hR[r]; } \
} while (0)
#define LD_B(it) do { \
    _Pragma("unroll") \
    for (int r = 0; r < 4; r++) { int i = tid + r * THR; \
        int kqs = i >> 10, rr = i & 1023, bl = rr >> 7, hh = (rr >> 1) & 63, k4 = i & 1; \
        lR[r] = __ldcg((const float4*)(g_l + ((size_t)(bt * 8 + bl) * H_DIM \
                        + kqs * 256 + (it) * 64 + hh) * 8) + k4); } \
    _Pragma("unroll") \
    for (int r = 0; r < 2; r++) { int i = tid + r * THR; \
        int kqs = i >> 9, hh = (i >> 3) & 63, f4 = i & 7; \
        wR2[r] = __ldg((const float4*)(W_a + (size_t)(kqs * 256 + (it) * 64 + hh) * H_DIM \
                        + gt * 32) + f4); } \
} while (0)
#define ST_B(buf) do { \
    _Pragma("unroll") \
    for (int r = 0; r < 4; r++) { int i = tid + r * THR; \
        int kqs = i >> 10, rr = i & 1023, bl = rr >> 7, hh = (rr >> 1) & 63, k4 = i & 1; \
        ((float4*)sL)[(((buf) * 2 + kqs) * 8 + bl) * 128 + hh * 2 + k4] = lR[r]; } \
    _Pragma("unroll") \
    for (int r = 0; r < 2; r++) { int i = tid + r * THR; \
        int kqs = i >> 9, hh = (i >> 3) & 63, f4 = i & 7; \
        ((float4*)sW)[((buf) * 2 + kqs) * 512 + hh * 8 + f4] = wR2[r]; } \
} while (0)

    for (int t = 0; t < T_DIM; t++) {
        // =============== Phase A ===============
        unsigned long long accA[4], accB[4];
        #pragma unroll
        for (int i = 0; i < 4; i++) { accA[i] = 0ull; accB[i] = 0ull; }

        LD_A(0);
        for (int i = tid; i < 64 * Ca; i += THR) {
            int b = i / Ca, c = i - b * Ca;
            sX[b * 8 + c] = XA[((size_t)b * Ca + c) * T_DIM + t];
        }
        for (int i = tid; i < 64 * Cb; i += THR) {
            int b = i / Cb, c = i - b * Cb;
            sX[512 + b * 8 + c] = XB[((size_t)b * Cb + c) * T_DIM + t];
        }
        ST_A(0);
        __syncthreads();

        #pragma unroll 1
        for (int it = 0; it < 4; it++) {
            if (it < 3) LD_A(it + 1);
            const int buf = it & 1;
            const float* Uf = sU + (buf * 2 + kq) * 4096;
            const ulonglong2* Hv = (const ulonglong2*)sH + (buf * 2 + kq) * 1024;
            #pragma unroll 8
            for (int hh = 0; hh < 64; hh++) {
                unsigned long long ua = pack2(Uf[hh * 32 + jl]);
                unsigned long long ub = pack2(Uf[2048 + hh * 32 + jl]);
                ulonglong2 h01 = Hv[hh * 16 + bq * 2 + 0];
                ulonglong2 h23 = Hv[hh * 16 + bq * 2 + 1];
                accA[0] = fma2(h01.x, ua, accA[0]);
                accA[1] = fma2(h01.y, ua, accA[1]);
                accA[2] = fma2(h23.x, ua, accA[2]);
                accA[3] = fma2(h23.y, ua, accA[3]);
                accB[0] = fma2(h01.x, ub, accB[0]);
                accB[1] = fma2(h01.y, ub, accB[1]);
                accB[2] = fma2(h23.x, ub, accB[2]);
                accB[3] = fma2(h23.y, ub, accB[3]);
            }
            if (it < 3) { __syncthreads(); ST_A((it + 1) & 1); __syncthreads(); }
        }

        // split-K reduction (exchange over buf0 region; last compute used buf1)
        if (kq == 1) {
            float4* dst = sEx + rec * 4;
            float2 q;
            q = unpack2(accA[0]); dst[0].x = q.x; dst[0].y = q.y;
            q = unpack2(accA[1]); dst[0].z = q.x; dst[0].w = q.y;
            q = unpack2(accA[2]); dst[1].x = q.x; dst[1].y = q.y;
            q = unpack2(accA[3]); dst[1].z = q.x; dst[1].w = q.y;
            q = unpack2(accB[0]); dst[2].x = q.x; dst[2].y = q.y;
            q = unpack2(accB[1]); dst[2].z = q.x; dst[2].w = q.y;
            q = unpack2(accB[2]); dst[3].x = q.x; dst[3].y = q.y;
            q = unpack2(accB[3]); dst[3].z = q.x; dst[3].w = q.y;
        }
        __syncthreads();
        if (kq == 0) {
            const float* src = (const float*)(sEx + rec * 4);
            float zA[8], zB[8];
            { float2 q;
              q = unpack2(accA[0]); zA[0] = q.x + src[0];  zA[1] = q.y + src[1];
              q = unpack2(accA[1]); zA[2] = q.x + src[2];  zA[3] = q.y + src[3];
              q = unpack2(accA[2]); zA[4] = q.x + src[4];  zA[5] = q.y + src[5];
              q = unpack2(accA[3]); zA[6] = q.x + src[6];  zA[7] = q.y + src[7];
              q = unpack2(accB[0]); zB[0] = q.x + src[8];  zB[1] = q.y + src[9];
              q = unpack2(accB[1]); zB[2] = q.x + src[10]; zB[3] = q.y + src[11];
              q = unpack2(accB[2]); zB[4] = q.x + src[12]; zB[5] = q.y + src[13];
              q = unpack2(accB[3]); zB[6] = q.x + src[14]; zB[7] = q.y + src[15]; }
            #pragma unroll
            for (int bl = 0; bl < 8; bl++) {
                int b = bq * 8 + bl;
                float pa = biasA, pb = biasB;
                for (int c = 0; c < Ca; c++) pa = fmaf(sX[b * 8 + c], wA[c], pa);
                for (int c = 0; c < Cb; c++) pb = fmaf(sX[512 + b * 8 + c], wB[c], pb);
                float za = zA[bl] + pa, zb = zB[bl] + pb;
                if (p == 1) {
                    g_f[b * H_DIM + j] = fsig(za);
                    g_o[b * H_DIM + j] = fsig(zb);
                } else {
                    int k = (p == 0) ? 0 : (p - 1);
                    g_l[((size_t)b * H_DIM + j) * 8 + k] = fsig(za) * ftanh(zb);
                }
            }
        }

        grid_barrier(2 * t + 1);

        // =============== Phase B ===============
        if (cta < 128) {
            unsigned long long acc[4] = {0ull, 0ull, 0ull, 0ull};
            float lg[8];
            #pragma unroll
            for (int i = 0; i < 8; i++) lg[i] = 0.f;

            LD_B(0); ST_B(0); __syncthreads();

            #pragma unroll 1
            for (int it = 0; it < 4; it++) {
                if (it < 3) LD_B(it + 1);
                const int buf = it & 1;
                const float* Wf = sW + (buf * 2 + kq) * 2048;
                const ulonglong2* Lv = (const ulonglong2*)sL + ((buf * 2 + kq) * 8 + bloc) * 128;
                if (kq == kq_own && it == it_own) {
                    int hl = gB & 63;
                    ulonglong2 v0 = Lv[hl * 2 + 0];
                    ulonglong2 v1 = Lv[hl * 2 + 1];
                    float2 q;
                    q = unpack2(v0.x); lg[0] = q.x; lg[1] = q.y;
                    q = unpack2(v0.y); lg[2] = q.x; lg[3] = q.y;
                    q = unpack2(v1.x); lg[4] = q.x; lg[5] = q.y;
                    q = unpack2(v1.y); lg[6] = q.x; lg[7] = q.y;
                }
                #pragma unroll 8
                for (int hh = 0; hh < 64; hh++) {
                    unsigned long long w2 = pack2(Wf[hh * 32 + gloc]);
                    ulonglong2 v0 = Lv[hh * 2 + 0];
                    ulonglong2 v1 = Lv[hh * 2 + 1];
                    acc[0] = fma2(v0.x, w2, acc[0]);
                    acc[1] = fma2(v0.y, w2, acc[1]);
                    acc[2] = fma2(v1.x, w2, acc[2]);
                    acc[3] = fma2(v1.y, w2, acc[3]);
                }
                if (it < 3) { __syncthreads(); ST_B((it + 1) & 1); __syncthreads(); }
            }

            // split-K reduction + lg hand-off (exchange over buf0 region)
            if (kq == 1) {
                float4* dst = sEx + rec * 4;
                float2 q;
                q = unpack2(acc[0]); dst[0].x = q.x; dst[0].y = q.y;
                q = unpack2(acc[1]); dst[0].z = q.x; dst[0].w = q.y;
                q = unpack2(acc[2]); dst[1].x = q.x; dst[1].y = q.y;
                q = unpack2(acc[3]); dst[1].z = q.x; dst[1].w = q.y;
                dst[2] = make_float4(lg[0], lg[1], lg[2], lg[3]);
                dst[3] = make_float4(lg[4], lg[5], lg[6], lg[7]);
            }
            __syncthreads();
            if (kq == 0) {
                const float* src = (const float*)(sEx + rec * 4);
                float a[8];
                { float2 q;
                  q = unpack2(acc[0]); a[0] = q.x + src[0]; a[1] = q.y + src[1];
                  q = unpack2(acc[1]); a[2] = q.x + src[2]; a[3] = q.y + src[3];
                  q = unpack2(acc[2]); a[4] = q.x + src[4]; a[5] = q.y + src[5];
                  q = unpack2(acc[3]); a[6] = q.x + src[6]; a[7] = q.y + src[7]; }
                if (kq_own == 1) {
                    #pragma unroll
                    for (int k = 0; k < 8; k++) lg[k] = src[8 + k];
                }
                float u[8], mx = -1e30f;
                #pragma unroll
                for (int k = 0; k < 8; k++) {
                    u[k] = ftanh(fmaf(a[k], c_reg, baB));
                    mx = fmaxf(mx, u[k]);
                }
                float es = 0.f, L = 0.f;
                #pragma unroll
                for (int k = 0; k < 8; k++) {
                    float e = __expf(u[k] - mx);
                    es += e;
                    L  += e * lg[k];
                }
                L /= es;
                int idx = bB_ * H_DIM + gB;
                float fv = __ldcg(&g_f[idx]);
                float ov = __ldcg(&g_o[idx]);
                c_reg = fmaf(fv, c_reg, L);
                float hn = ov * ftanh(c_reg);
                g_hT[gB * B_DIM + bB_] = hn;
                out[(size_t)B_DIM * H_DIM + ((size_t)bB_ * T_DIM + t) * H_DIM + gB] = hn;
                if (t == T_DIM - 1) out[bB_ * H_DIM + gB] = hn;
            }
        }

        grid_barrier(2 * t + 2);
    }
#undef LD_A
#undef ST_A
#undef LD_B
#undef ST_B
}

// ---------------------------------------------------------------------------
extern "C" void kernel_launch(void* const* d_in, const int* in_sizes, int n_in,
                              void* d_out, int out_size) {
    (void)in_sizes; (void)n_in; (void)out_size;
    Ptrs P;
    for (int i = 0; i < 28; i++) P.p[i] = (const float*)d_in[i];

    cudaFuncSetAttribute(main_kernel,
                         cudaFuncAttributeMaxDynamicSharedMemorySize, DYN_SMEM);

    reset_kernel<<<64, 256>>>();
    main_kernel<<<NBLK, THR, DYN_SMEM>>>(P, (float*)d_out);
}